// round 7
// baseline (speedup 1.0000x reference)
#include <cuda_runtime.h>
#include <math.h>

#define T_STEPS 1024
#define NB 128
#define FD 128
#define HD 128

// Scratch: 8 precomputed floats per (b,t):
//  [0:4) = x_t @ W_in_x^T + b_in   (x-part of y)
//  [4:8) = vqc(x_t @ W_x^T + b_x, vqc_w[2])  (fully h-independent)
__device__ float g_xpre[NB * T_STEPS * 8];

typedef unsigned long long u64;

__device__ __forceinline__ u64 pack2(float lo, float hi) {
    u64 r;
    asm("mov.b64 %0, {%1, %2};" : "=l"(r) : "f"(lo), "f"(hi));
    return r;
}
__device__ __forceinline__ void unpack2(u64 v, float& lo, float& hi) {
    asm("mov.b64 {%0, %1}, %2;" : "=f"(lo), "=f"(hi) : "l"(v));
}
// Blackwell packed fp32 pair ops
__device__ __forceinline__ u64 fma2(u64 a, u64 b, u64 c) {
    u64 r;
    asm("fma.rn.f32x2 %0, %1, %2, %3;" : "=l"(r) : "l"(a), "l"(b), "l"(c));
    return r;
}

// ---------------------------------------------------------------------------
// Pre-pass: one warp per (b,t) row, grid-stride. Memory bound (~64MB read).
// ---------------------------------------------------------------------------
__global__ void __launch_bounds__(256) qgru_prepass(
    const float* __restrict__ x,
    const float* __restrict__ W_in, const float* __restrict__ b_in,
    const float* __restrict__ W_x,  const float* __restrict__ b_x,
    const float* __restrict__ vqc_w)
{
    const int lane = threadIdx.x & 31;
    const int gw   = (blockIdx.x * blockDim.x + threadIdx.x) >> 5;
    const int nw   = (gridDim.x * blockDim.x) >> 5;

    float wt[8][4];
#pragma unroll
    for (int k = 0; k < 4; k++) {
#pragma unroll
        for (int i = 0; i < 4; i++) {
            wt[k][i]     = W_in[k * (HD + FD) + HD + lane * 4 + i];
            wt[4 + k][i] = W_x[k * FD + lane * 4 + i];
        }
    }
    float bi[8], w2[4];
#pragma unroll
    for (int k = 0; k < 4; k++) {
        bi[k]     = b_in[k];
        bi[4 + k] = b_x[k];
        w2[k]     = vqc_w[2 * 4 + k];
    }

    const int NROWS = NB * T_STEPS;
#pragma unroll 2
    for (int row = gw; row < NROWS; row += nw) {
        float4 xv = *reinterpret_cast<const float4*>(x + (size_t)row * FD + lane * 4);
        float s[8];
#pragma unroll
        for (int k = 0; k < 8; k++) {
            s[k] = wt[k][0] * xv.x;
            s[k] = fmaf(wt[k][1], xv.y, s[k]);
            s[k] = fmaf(wt[k][2], xv.z, s[k]);
            s[k] = fmaf(wt[k][3], xv.w, s[k]);
        }
#pragma unroll
        for (int off = 16; off; off >>= 1) {
#pragma unroll
            for (int k = 0; k < 8; k++)
                s[k] += __shfl_xor_sync(0xffffffffu, s[k], off);
        }
        if (lane == 0) {
            float c0 = __cosf(s[4] + bi[4] + w2[0]);
            float c1 = __cosf(s[5] + bi[5] + w2[1]);
            float c2 = __cosf(s[6] + bi[6] + w2[2]);
            float c3 = __cosf(s[7] + bi[7] + w2[3]);
            float z1 = c0 * c1;
            float z2 = z1 * c2;
            float4 o0 = make_float4(s[0] + bi[0], s[1] + bi[1],
                                    s[2] + bi[2], s[3] + bi[3]);
            float4 o1 = make_float4(c1 * c2 * c3, z1, z2, z2 * c3);
            float4* op = reinterpret_cast<float4*>(g_xpre + (size_t)row * 8);
            op[0] = o0;
            op[1] = o1;
        }
    }
}

// ---------------------------------------------------------------------------
// Sequential recurrence: ONE WARP per batch row. Lane l owns h[4l..4l+3] in
// REGISTERS. No smem, no barriers. Per step:
//   - 8 dot sums via packed FFMA2 partials (h stays in registers)
//   - 9-shuffle value-splitting reduction; sum k lands in lane quad 4k
//   - 1 warp-wide MUFU.COS produces all 12 gate cosines; 12 shfl broadcasts
//   - each lane computes its 4 output columns (packed-f32x2 gate dots)
//   - merged-division GRU update: h'=(Ez(1-Eu)+h(1+Eu))/((1+Eu)(1+Ez))
// ---------------------------------------------------------------------------
__global__ void __launch_bounds__(32, 1) qgru_seq(
    const float* __restrict__ W_in, const float* __restrict__ W_h,
    const float* __restrict__ b_h,
    const float* __restrict__ W_out, const float* __restrict__ b_out,
    const float* __restrict__ vqc_w,
    float* __restrict__ out)
{
    const int b  = blockIdx.x;
    const int l  = threadIdx.x;     // 0..31
    const int k  = l >> 2;          // sum index this lane ends up owning
    const int r4 = l & 3;

    // ---- dot weights: wd[kk] covers h[4l..4l+3] for sum kk
    // kk<4 -> W_in[kk, 0:128] (h-part of y); kk>=4 -> W_h[kk-4, :]
    u64 wd0[8], wd1[8];
#pragma unroll
    for (int kk = 0; kk < 8; kk++) {
        const float* row = (kk < 4) ? (W_in + kk * (HD + FD))
                                    : (W_h + (kk - 4) * HD);
        float4 wv = *reinterpret_cast<const float4*>(row + 4 * l);
        wd0[kk] = pack2(wv.x, wv.y);
        wd1[kk] = pack2(wv.z, wv.w);
    }

    // ---- W_out rows for this lane's 4 columns, packed per column pair
    u64 woP[2][4], boP[2];
#pragma unroll
    for (int p = 0; p < 2; p++) {
        int j0 = 4 * l + 2 * p, j1 = j0 + 1;
#pragma unroll
        for (int i = 0; i < 4; i++)
            woP[p][i] = pack2(W_out[j0 * 4 + i], W_out[j1 * 4 + i]);
        boP[p] = pack2(b_out[j0], b_out[j1]);
    }

    // ---- cosine role (loop-invariant additive constant)
    // k<4: r4==0 -> cr_k (+vqc_w[0][k]); r4==1 -> cz_k (+vqc_w[1][k])
    // k>=4: r4==0 -> ch_{k-4} (+vqc_w[3][k-4] + b_h[k-4])
    float cadd = 0.0f;
    if (k < 4) {
        if (r4 == 0) cadd = vqc_w[k];
        else if (r4 == 1) cadd = vqc_w[4 + k];
    } else if (r4 == 0) {
        cadd = vqc_w[12 + (k - 4)] + b_h[k - 4];
    }
    const bool use_p = (k < 4);

    const int hi = (l >> 4) & 1;
    const int h3 = (l >> 3) & 1;
    const int h2 = (l >> 2) & 1;

    // h in registers
    float hc0 = 0.0f, hc1 = 0.0f, hc2 = 0.0f, hc3 = 0.0f;
    u64 h01 = 0ull, h23 = 0ull;

    // c_last = zeros
    *reinterpret_cast<float4*>(
        out + (size_t)NB * T_STEPS * HD + (size_t)NB * HD + b * HD + 4 * l) =
        make_float4(0.f, 0.f, 0.f, 0.f);

    const float4* __restrict__ xp =
        reinterpret_cast<const float4*>(g_xpre + (size_t)b * T_STEPS * 8);
    float4 p0 = xp[0], p1 = xp[1];

    float* __restrict__ obase = out + (size_t)b * T_STEPS * HD + 4 * l;

#pragma unroll 1
    for (int t = 0; t < T_STEPS; t++) {
        // select this lane's y-offset component (off critical path)
        float pc = (k == 0) ? p0.x : (k == 1) ? p0.y : (k == 2) ? p0.z : p0.w;

        // prefetch next step's xpre (uniform broadcast LDG, L2-resident)
        const int tn = (t + 1 < T_STEPS) ? (t + 1) : (T_STEPS - 1);
        float4 p0n = xp[2 * tn];
        float4 p1n = xp[2 * tn + 1];

        // ---- partial dots over this lane's 4 h elements
        float v[8];
#pragma unroll
        for (int kk = 0; kk < 8; kk++) {
            u64 acc = fma2(h23, wd1[kk], 0ull);
            acc = fma2(h01, wd0[kk], acc);
            float lo, hiF;
            unpack2(acc, lo, hiF);
            v[kk] = lo + hiF;
        }

        // ---- value-splitting butterfly: 9 shuffles, 5 rounds
        // round 1 (xor 16): keep sums [hi*4 .. hi*4+4)
        float u4_0, u4_1, u4_2, u4_3;
        {
            float s0 = hi ? v[0] : v[4];
            float s1 = hi ? v[1] : v[5];
            float s2 = hi ? v[2] : v[6];
            float s3 = hi ? v[3] : v[7];
            float r0 = __shfl_xor_sync(0xffffffffu, s0, 16);
            float r1 = __shfl_xor_sync(0xffffffffu, s1, 16);
            float r2 = __shfl_xor_sync(0xffffffffu, s2, 16);
            float r3 = __shfl_xor_sync(0xffffffffu, s3, 16);
            u4_0 = (hi ? v[4] : v[0]) + r0;
            u4_1 = (hi ? v[5] : v[1]) + r1;
            u4_2 = (hi ? v[6] : v[2]) + r2;
            u4_3 = (hi ? v[7] : v[3]) + r3;
        }
        // round 2 (xor 8)
        float u2_0, u2_1;
        {
            float s0 = h3 ? u4_0 : u4_2;
            float s1 = h3 ? u4_1 : u4_3;
            float r0 = __shfl_xor_sync(0xffffffffu, s0, 8);
            float r1 = __shfl_xor_sync(0xffffffffu, s1, 8);
            u2_0 = (h3 ? u4_2 : u4_0) + r0;
            u2_1 = (h3 ? u4_3 : u4_1) + r1;
        }
        // round 3 (xor 4)
        float s;
        {
            float s0 = h2 ? u2_0 : u2_1;
            float r0 = __shfl_xor_sync(0xffffffffu, s0, 4);
            s = (h2 ? u2_1 : u2_0) + r0;
        }
        // rounds 4,5
        s += __shfl_xor_sync(0xffffffffu, s, 2);
        s += __shfl_xor_sync(0xffffffffu, s, 1);
        // now s = fully-reduced sum (l>>2), replicated in the lane quad

        // ---- one warp-wide cosine for all 12 gates
        float arg = s + cadd + (use_p ? pc : 0.0f);
        float cv  = __cosf(arg);

        float cr0 = __shfl_sync(0xffffffffu, cv, 0);
        float cr1 = __shfl_sync(0xffffffffu, cv, 4);
        float cr2 = __shfl_sync(0xffffffffu, cv, 8);
        float cr3 = __shfl_sync(0xffffffffu, cv, 12);
        float cz0 = __shfl_sync(0xffffffffu, cv, 1);
        float cz1 = __shfl_sync(0xffffffffu, cv, 5);
        float cz2 = __shfl_sync(0xffffffffu, cv, 9);
        float cz3 = __shfl_sync(0xffffffffu, cv, 13);
        float ch0 = __shfl_sync(0xffffffffu, cv, 16);
        float ch1 = __shfl_sync(0xffffffffu, cv, 20);
        float ch2 = __shfl_sync(0xffffffffu, cv, 24);
        float ch3 = __shfl_sync(0xffffffffu, cv, 28);

        // ---- z-expectation vectors (uniform): (C1C2C3, C0C1, C0C1C2, C0C1C2C3)
        float rm  = cr1 * cr2;
        float zr0 = rm * cr3, zr1 = cr0 * cr1, zr2 = cr0 * rm, zr3 = zr2 * cr3;
        float zm  = cz1 * cz2;
        float zz0 = zm * cz3, zz1 = cz0 * cz1, zz2 = cz0 * zm, zz3 = zz2 * cz3;
        float hm  = ch1 * ch2;
        float zh0 = hm * ch3, zh1 = ch0 * ch1, zh2 = ch0 * hm, zh3 = zh2 * ch3;

        // pack uniform vectors for paired-column gate dots
        u64 zrP0 = pack2(zr0, zr0), zrP1 = pack2(zr1, zr1);
        u64 zrP2 = pack2(zr2, zr2), zrP3 = pack2(zr3, zr3);
        u64 zzP0 = pack2(zz0, zz0), zzP1 = pack2(zz1, zz1);
        u64 zzP2 = pack2(zz2, zz2), zzP3 = pack2(zz3, zz3);
        u64 zhP0 = pack2(zh0, zh0), zhP1 = pack2(zh1, zh1);
        u64 zhP2 = pack2(zh2, zh2), zhP3 = pack2(zh3, zh3);
        u64 pxP0 = pack2(p1.x, p1.x), pxP1 = pack2(p1.y, p1.y);
        u64 pxP2 = pack2(p1.z, p1.z), pxP3 = pack2(p1.w, p1.w);

        float o_r[4], o_z[4], o_h[4], o_x[4];
#pragma unroll
        for (int p = 0; p < 2; p++) {
            u64 ar = fma2(zrP0, woP[p][0], boP[p]);
            ar = fma2(zrP1, woP[p][1], ar);
            ar = fma2(zrP2, woP[p][2], ar);
            ar = fma2(zrP3, woP[p][3], ar);
            unpack2(ar, o_r[2 * p], o_r[2 * p + 1]);

            u64 az = fma2(zzP0, woP[p][0], boP[p]);
            az = fma2(zzP1, woP[p][1], az);
            az = fma2(zzP2, woP[p][2], az);
            az = fma2(zzP3, woP[p][3], az);
            unpack2(az, o_z[2 * p], o_z[2 * p + 1]);

            u64 ah = fma2(zhP0, woP[p][0], boP[p]);
            ah = fma2(zhP1, woP[p][1], ah);
            ah = fma2(zhP2, woP[p][2], ah);
            ah = fma2(zhP3, woP[p][3], ah);
            unpack2(ah, o_h[2 * p], o_h[2 * p + 1]);

            u64 ax = fma2(pxP0, woP[p][0], boP[p]);
            ax = fma2(pxP1, woP[p][1], ax);
            ax = fma2(pxP2, woP[p][2], ax);
            ax = fma2(pxP3, woP[p][3], ax);
            unpack2(ax, o_x[2 * p], o_x[2 * p + 1]);
        }

        // ---- per-column MUFU tail (merged-division GRU update)
        float hcv[4] = {hc0, hc1, hc2, hc3};
        float hn[4];
#pragma unroll
        for (int c = 0; c < 4; c++) {
            float Er = __expf(-o_r[c]);
            float Ez = __expf(-o_z[c]);
            float uu = o_x[c] + __fdividef(o_h[c], 1.0f + Er);
            float Eu = __expf(-2.0f * uu);
            float t2 = 1.0f + Eu;
            float num = fmaf(Ez, 1.0f - Eu, hcv[c] * t2);
            float den = t2 * (1.0f + Ez);
            hn[c] = __fdividef(num, den);
        }

        // store hidden_seq[b, t, 4l..4l+3] (coalesced STG.128, off-chain)
        *reinterpret_cast<float4*>(obase + (size_t)t * HD) =
            make_float4(hn[0], hn[1], hn[2], hn[3]);

        hc0 = hn[0]; hc1 = hn[1]; hc2 = hn[2]; hc3 = hn[3];
        h01 = pack2(hc0, hc1);
        h23 = pack2(hc2, hc3);
        p0 = p0n; p1 = p1n;
    }

    // h_last
    *reinterpret_cast<float4*>(
        out + (size_t)NB * T_STEPS * HD + b * HD + 4 * l) =
        make_float4(hc0, hc1, hc2, hc3);
}

extern "C" void kernel_launch(void* const* d_in, const int* in_sizes, int n_in,
                              void* d_out, int out_size) {
    const float* x     = (const float*)d_in[0];
    const float* W_in  = (const float*)d_in[1];
    const float* b_in  = (const float*)d_in[2];
    const float* W_x   = (const float*)d_in[3];
    const float* b_x   = (const float*)d_in[4];
    const float* W_h   = (const float*)d_in[5];
    const float* b_h   = (const float*)d_in[6];
    const float* W_out = (const float*)d_in[7];
    const float* b_out = (const float*)d_in[8];
    const float* vqcw  = (const float*)d_in[9];
    float* out = (float*)d_out;

    qgru_prepass<<<1184, 256>>>(x, W_in, b_in, W_x, b_x, vqcw);
    qgru_seq<<<NB, 32>>>(W_in, W_h, b_h, W_out, b_out, vqcw, out);
}

// round 8
// speedup vs baseline: 1.1583x; 1.1583x over previous
#include <cuda_runtime.h>
#include <math.h>

#define T_STEPS 1024
#define NB 128
#define FD 128
#define HD 128

typedef unsigned long long u64;

__device__ __forceinline__ u64 pack2(float lo, float hi) {
    u64 r;
    asm("mov.b64 %0, {%1, %2};" : "=l"(r) : "f"(lo), "f"(hi));
    return r;
}
__device__ __forceinline__ void unpack2(u64 v, float& lo, float& hi) {
    asm("mov.b64 {%0, %1}, %2;" : "=f"(lo), "=f"(hi) : "l"(v));
}
__device__ __forceinline__ u64 fma2(u64 a, u64 b, u64 c) {
    u64 r;
    asm("fma.rn.f32x2 %0, %1, %2, %3;" : "=l"(r) : "l"(a), "l"(b), "l"(c));
    return r;
}
__device__ __forceinline__ u64 add2(u64 a, u64 b) {
    u64 r;
    asm("add.rn.f32x2 %0, %1, %2;" : "=l"(r) : "l"(a), "l"(b));
    return r;
}
__device__ __forceinline__ float ex2f(float x) {
    float r;
    asm("ex2.approx.f32 %0, %1;" : "=f"(r) : "f"(x));
    return r;
}
__device__ __forceinline__ float rcpf(float x) {
    float r;
    asm("rcp.approx.f32 %0, %1;" : "=f"(r) : "f"(x));
    return r;
}

// ---------------------------------------------------------------------------
// Fused kernel: ONE CTA per batch row (128 threads / 4 warps).
// Phase 1: compute this row's xpre (8 floats per t) straight into smem:
//   xs[t*8 + 0:4) = x_t @ W_in_x^T + b_in      (x-part of y)
//   xs[t*8 + 4:8) = vqc(x_t @ W_x^T + b_x, w2) (closed-form, h-independent)
//   One warp per t-row; R7's 5-round value-split butterfly; 4-deep LDG
//   prefetch for DRAM MLP.
// Phase 2: 1024 sequential GRU steps (R5 structure):
//   lane = 8m+sub owns sums {2m,2m+1} over h[16sub..16sub+16);
//   3-shuffle value-split reduction; one warp-wide MUFU.COS -> 12 cosines
//   distributed via per-warp smem slot; ex2-folded merged-division update.
// ---------------------------------------------------------------------------
__global__ void __launch_bounds__(128, 1) qgru_fused(
    const float* __restrict__ x,
    const float* __restrict__ W_in, const float* __restrict__ b_in,
    const float* __restrict__ W_x,  const float* __restrict__ b_x,
    const float* __restrict__ W_h,  const float* __restrict__ b_h,
    const float* __restrict__ W_out, const float* __restrict__ b_out,
    const float* __restrict__ vqc_w,
    float* __restrict__ out)
{
    const int b    = blockIdx.x;
    const int j    = threadIdx.x;
    const int lane = j & 31;
    const int wid  = j >> 5;

    __shared__ __align__(16) float xs[T_STEPS * 8];     // 32 KB xpre for row b
    __shared__ __align__(16) float h_sh[2][HD];
    __shared__ __align__(16) float cos_sh[4][16];       // slots 0..11 used

    // =========================== Phase 1 ===========================
    {
        const int k  = lane >> 2;          // sum this lane ends up owning
        const int hi = (lane >> 4) & 1;
        const int h3 = (lane >> 3) & 1;
        const int h2 = (lane >> 2) & 1;

        // weights: sum kk<4 -> W_in[kk, HD + 4*lane ..); kk>=4 -> W_x[kk-4, 4*lane..)
        u64 wt0[8], wt1[8];
#pragma unroll
        for (int kk = 0; kk < 8; kk++) {
            const float* row = (kk < 4) ? (W_in + kk * (HD + FD) + HD)
                                        : (W_x + (kk - 4) * FD);
            float4 wv = *reinterpret_cast<const float4*>(row + 4 * lane);
            wt0[kk] = pack2(wv.x, wv.y);
            wt1[kk] = pack2(wv.z, wv.w);
        }
        const float bias_l = (k < 4) ? b_in[k]
                                     : (b_x[k - 4] + vqc_w[8 + (k - 4)]);

        const float* xrow = x + (size_t)b * T_STEPS * FD + 4 * lane;

        auto prep_row = [&](float4 xv, int t) {
            u64 xv01 = pack2(xv.x, xv.y);
            u64 xv23 = pack2(xv.z, xv.w);
            float v[8];
#pragma unroll
            for (int kk = 0; kk < 8; kk++) {
                u64 acc = fma2(xv01, wt0[kk], fma2(xv23, wt1[kk], 0ull));
                float lo, hiF;
                unpack2(acc, lo, hiF);
                v[kk] = lo + hiF;
            }
            // 5-round value-splitting butterfly (9 shuffles), from R7 (proven)
            float u4_0, u4_1, u4_2, u4_3;
            {
                float s0 = hi ? v[0] : v[4];
                float s1 = hi ? v[1] : v[5];
                float s2 = hi ? v[2] : v[6];
                float s3 = hi ? v[3] : v[7];
                float r0 = __shfl_xor_sync(0xffffffffu, s0, 16);
                float r1 = __shfl_xor_sync(0xffffffffu, s1, 16);
                float r2 = __shfl_xor_sync(0xffffffffu, s2, 16);
                float r3 = __shfl_xor_sync(0xffffffffu, s3, 16);
                u4_0 = (hi ? v[4] : v[0]) + r0;
                u4_1 = (hi ? v[5] : v[1]) + r1;
                u4_2 = (hi ? v[6] : v[2]) + r2;
                u4_3 = (hi ? v[7] : v[3]) + r3;
            }
            float u2_0, u2_1;
            {
                float s0 = h3 ? u4_0 : u4_2;
                float s1 = h3 ? u4_1 : u4_3;
                float r0 = __shfl_xor_sync(0xffffffffu, s0, 8);
                float r1 = __shfl_xor_sync(0xffffffffu, s1, 8);
                u2_0 = (h3 ? u4_2 : u4_0) + r0;
                u2_1 = (h3 ? u4_3 : u4_1) + r1;
            }
            float s;
            {
                float s0 = h2 ? u2_0 : u2_1;
                float r0 = __shfl_xor_sync(0xffffffffu, s0, 4);
                s = (h2 ? u2_1 : u2_0) + r0;
            }
            s += __shfl_xor_sync(0xffffffffu, s, 2);
            s += __shfl_xor_sync(0xffffffffu, s, 1);
            // sum k (=lane>>2) replicated across the lane quad

            float val = s + bias_l;
            float cv  = __cosf(val);   // used only by k>=4 roles
            float c0 = __shfl_sync(0xffffffffu, cv, 16);
            float c1 = __shfl_sync(0xffffffffu, cv, 20);
            float c2 = __shfl_sync(0xffffffffu, cv, 24);
            float c3 = __shfl_sync(0xffffffffu, cv, 28);

            if ((lane & 3) == 0) {
                float sval;
                if (k < 4) {
                    sval = val;                      // y-offset component k
                } else {
                    float z1 = c0 * c1, z2 = z1 * c2;
                    sval = (k == 4) ? c1 * c2 * c3
                         : (k == 5) ? z1
                         : (k == 6) ? z2
                                    : z2 * c3;       // k == 7
                }
                xs[t * 8 + k] = sval;
            }
        };

        // 4-deep prefetch; each warp handles rows t = wid + 4*i
        float4 c0v = *reinterpret_cast<const float4*>(xrow + (size_t)(wid + 0)  * FD);
        float4 c1v = *reinterpret_cast<const float4*>(xrow + (size_t)(wid + 4)  * FD);
        float4 c2v = *reinterpret_cast<const float4*>(xrow + (size_t)(wid + 8)  * FD);
        float4 c3v = *reinterpret_cast<const float4*>(xrow + (size_t)(wid + 12) * FD);

#pragma unroll 1
        for (int ib = 0; ib < 64; ib++) {
            const int ibn = (ib < 63) ? ib + 1 : 63;
            float4 n0 = *reinterpret_cast<const float4*>(xrow + (size_t)(wid + 16 * ibn + 0)  * FD);
            float4 n1 = *reinterpret_cast<const float4*>(xrow + (size_t)(wid + 16 * ibn + 4)  * FD);
            float4 n2 = *reinterpret_cast<const float4*>(xrow + (size_t)(wid + 16 * ibn + 8)  * FD);
            float4 n3 = *reinterpret_cast<const float4*>(xrow + (size_t)(wid + 16 * ibn + 12) * FD);

            const int t0 = wid + 16 * ib;
            prep_row(c0v, t0 + 0);
            prep_row(c1v, t0 + 4);
            prep_row(c2v, t0 + 8);
            prep_row(c3v, t0 + 12);

            c0v = n0; c1v = n1; c2v = n2; c3v = n3;
        }
    }

    // =========================== Phase 2 ===========================
    const int m   = lane >> 3;    // sum pair {2m, 2m+1}
    const int sub = lane & 7;     // h slice [16*sub, 16*sub+16)

    // packed weights for sums k0=2m (A) and k1=2m+1 (B) over 16 h elems
    const int k0 = 2 * m, k1 = 2 * m + 1;
    const float* r0 = (k0 < 4) ? (W_in + k0 * (HD + FD)) : (W_h + (k0 - 4) * HD);
    const float* r1 = (k1 < 4) ? (W_in + k1 * (HD + FD)) : (W_h + (k1 - 4) * HD);
    u64 wA[8], wB[8];
#pragma unroll
    for (int i = 0; i < 8; i++) {
        wA[i] = pack2(r0[sub * 16 + 2 * i], r0[sub * 16 + 2 * i + 1]);
        wB[i] = pack2(r1[sub * 16 + 2 * i], r1[sub * 16 + 2 * i + 1]);
    }

    // W_out rows prescaled: RZ by log2e (feeds exp(-o)), HX by 2*log2e (feeds exp(-2u))
    const float L2E = 1.4426950408889634f;
    float woRZ[4], woHX[4];
#pragma unroll
    for (int kk = 0; kk < 4; kk++) {
        float w = W_out[j * 4 + kk];
        woRZ[kk] = w * L2E;
        woHX[kk] = w * (2.0f * L2E);
    }
    const float bof  = b_out[j];
    const float boRZ = bof * L2E;
    const float boHX = bof * (2.0f * L2E);

    // cosine role: after the 3-shuffle split, lanes 8m+{0..3} hold sum 2m,
    // lanes 8m+{4..7} hold sum 2m+1.
    const int k_owned = 2 * m + ((sub >> 2) & 1);
    int slot = -1;
    float cadd = 0.0f;
    if (m < 2) {
        if ((sub & 3) == 0)      { slot = k_owned;     cadd = vqc_w[k_owned]; }
        else if ((sub & 3) == 1) { slot = 4 + k_owned; cadd = vqc_w[4 + k_owned]; }
    } else {
        int kk = k_owned - 4;
        if ((sub & 3) == 0)      { slot = 8 + kk; cadd = vqc_w[12 + kk] + b_h[kk]; }
    }
    const bool use_p = (m < 2);
    const int  pidx  = k_owned & 3;

    float hj = 0.0f;
    h_sh[0][j] = 0.0f;

    // c_last = zeros
    out[(size_t)NB * T_STEPS * HD + (size_t)NB * HD + b * HD + j] = 0.0f;

    float* __restrict__ orow = out + (size_t)b * T_STEPS * HD + j;
    float* cbuf = cos_sh[wid];

    __syncthreads();   // phase boundary: xs + h_sh[0] ready

    float prev = 0.0f;

#pragma unroll 1
    for (int t = 0; t < T_STEPS; t++) {
        // h reads first: 4 LDS.128 per lane
        const ulonglong2* hp = reinterpret_cast<const ulonglong2*>(
            h_sh[t & 1] + sub * 16);
        ulonglong2 q0 = hp[0];
        ulonglong2 q1 = hp[1];
        ulonglong2 q2 = hp[2];
        ulonglong2 q3 = hp[3];

        // previous step's hidden-seq store, off the pre-barrier path
        if (t) orow[(size_t)(t - 1) * HD] = prev;

        // h-independent work off the critical path (o_x prescaled by 2*log2e)
        float4 P1 = *reinterpret_cast<const float4*>(xs + t * 8 + 4);
        float pc  = xs[t * 8 + pidx];
        float o_x = fmaf(P1.x, woHX[0],
                    fmaf(P1.y, woHX[1], fmaf(P1.z, woHX[2],
                    fmaf(P1.w, woHX[3], boHX))));

        u64 aA0 = 0ull, aA1 = 0ull, aB0 = 0ull, aB1 = 0ull;
        aA0 = fma2(q0.x, wA[0], aA0); aA1 = fma2(q0.y, wA[1], aA1);
        aB0 = fma2(q0.x, wB[0], aB0); aB1 = fma2(q0.y, wB[1], aB1);
        aA0 = fma2(q1.x, wA[2], aA0); aA1 = fma2(q1.y, wA[3], aA1);
        aB0 = fma2(q1.x, wB[2], aB0); aB1 = fma2(q1.y, wB[3], aB1);
        aA0 = fma2(q2.x, wA[4], aA0); aA1 = fma2(q2.y, wA[5], aA1);
        aB0 = fma2(q2.x, wB[4], aB0); aB1 = fma2(q2.y, wB[5], aB1);
        aA0 = fma2(q3.x, wA[6], aA0); aA1 = fma2(q3.y, wA[7], aA1);
        aB0 = fma2(q3.x, wB[6], aB0); aB1 = fma2(q3.y, wB[7], aB1);

        aA0 = add2(aA0, aA1);
        aB0 = add2(aB0, aB1);
        float alo, ahi, blo, bhi;
        unpack2(aA0, alo, ahi);
        unpack2(aB0, blo, bhi);
        float sA = alo + ahi;
        float sB = blo + bhi;

        // 3-shuffle value-splitting reduction over the 8-lane group
        float send = (sub & 4) ? sA : sB;
        float recv = __shfl_xor_sync(0xffffffffu, send, 4);
        float s = ((sub & 4) ? sB : sA) + recv;
        s += __shfl_xor_sync(0xffffffffu, s, 2);
        s += __shfl_xor_sync(0xffffffffu, s, 1);

        // one warp-wide cosine computes this warp's 12 gate cosines
        float arg = s + cadd + (use_p ? pc : 0.0f);
        float cv  = __cosf(arg);
        if (slot >= 0) cbuf[slot] = cv;
        __syncwarp();

        float4 CR = *reinterpret_cast<const float4*>(cbuf + 0);
        float4 CZ = *reinterpret_cast<const float4*>(cbuf + 4);
        float4 CH = *reinterpret_cast<const float4*>(cbuf + 8);

        // z-expectations after CNOT ring: (C1C2C3, C0C1, C0C1C2, C0C1C2C3)
        float rm = CR.y * CR.z;
        float rA = CR.x * CR.y, rB = CR.x * rm;
        float o_r = fmaf(rm * CR.w, woRZ[0],
                    fmaf(rA, woRZ[1], fmaf(rB, woRZ[2],
                    fmaf(rB * CR.w, woRZ[3], boRZ))));
        float Er = ex2f(-o_r);                 // = exp(-o_r_unscaled)

        float hm = CH.y * CH.z;
        float hA = CH.x * CH.y, hB = CH.x * hm;
        float o_h = fmaf(hm * CH.w, woHX[0],
                    fmaf(hA, woHX[1], fmaf(hB, woHX[2],
                    fmaf(hB * CH.w, woHX[3], boHX))));

        float zm = CZ.y * CZ.z;
        float zA = CZ.x * CZ.y, zB = CZ.x * zm;
        float o_z = fmaf(zm * CZ.w, woRZ[0],
                    fmaf(zA, woRZ[1], fmaf(zB, woRZ[2],
                    fmaf(zB * CZ.w, woRZ[3], boRZ))));
        float Ez = ex2f(-o_z);

        // u2 = 2*log2e*(o_x + o_h*r), r = sigmoid(o_r)
        float r  = rcpf(1.0f + Er);
        float u2 = fmaf(o_h, r, o_x);
        float Eu = ex2f(-u2);                  // = exp(-2u)

        // h' = (Ez(1-Eu) + h(1+Eu)) / ((1+Eu)(1+Ez))
        float t2  = 1.0f + Eu;
        float num = fmaf(Ez, 1.0f - Eu, hj * t2);
        float den = t2 * (1.0f + Ez);
        hj = num * rcpf(den);

        h_sh[(t + 1) & 1][j] = hj;        // publish to other lanes

        __syncthreads();
        prev = hj;
    }

    orow[(size_t)(T_STEPS - 1) * HD] = prev;
    // h_last
    out[(size_t)NB * T_STEPS * HD + b * HD + j] = hj;
}

extern "C" void kernel_launch(void* const* d_in, const int* in_sizes, int n_in,
                              void* d_out, int out_size) {
    const float* x     = (const float*)d_in[0];
    const float* W_in  = (const float*)d_in[1];
    const float* b_in  = (const float*)d_in[2];
    const float* W_x   = (const float*)d_in[3];
    const float* b_x   = (const float*)d_in[4];
    const float* W_h   = (const float*)d_in[5];
    const float* b_h   = (const float*)d_in[6];
    const float* W_out = (const float*)d_in[7];
    const float* b_out = (const float*)d_in[8];
    const float* vqcw  = (const float*)d_in[9];
    float* out = (float*)d_out;

    qgru_fused<<<NB, HD>>>(x, W_in, b_in, W_x, b_x, W_h, b_h,
                           W_out, b_out, vqcw, out);
}